// round 11
// baseline (speedup 1.0000x reference)
#include <cuda_runtime.h>
#include <cuda_fp16.h>
#include <cstdint>

// Block-circulant linear via length-4 DFT diagonalization (6/16 dense work),
// fp16 operands, f32 accumulation, fragment-order scratch.
// R11: 16 warps (512 threads), warp tile 16b x 32gy -> 4 warps/SMSP for
//      latency hiding; same crossbar + tensor floors as R9/R10.
//
//   u0=a+b+c+d, u1r=a-c, u1i=d-b, u2=a-b+c-d  (per x block)
//   P0=Fe0/4, P2=Fe2/4, P1r=(e0-e2)/2, P1i=(e3-e1)/2, P1n=-P1i
//   F0=sum P0*u0 ; F2=sum P2*u2
//   F1r=sum P1r*u1r + P1n*u1i ; F1i=sum P1i*u1r + P1r*u1i
//   o0=F0+F1r+F2  o1=F0-F1i-F2  o2=F0-F1r+F2  o3=F0+F1i-F2

#define B_DIM 4096
#define GX 1024
#define GY 1024
#define N_DIM 4096

// A tile (per bmt,kt): [c(4)][mt(8)][kstep(2)][lane(32)][reg(4)] f16x2 = 32KB
// E tile (per yt, kt): [p(5)][ntp(4)][kstep(2)][lane(32)][4] f16x2 = 20KB
#define A_TILE_U32 8192
#define E_TILE_U32 5120
__device__ uint32_t g_U[(size_t)32 * 32 * A_TILE_U32];   // 32 MB
__device__ uint32_t g_E[(size_t)16 * 32 * E_TILE_U32];   // 10 MB

__device__ __forceinline__ uint32_t pack_h2(float lo, float hi) {
    __half2 h = __floats2half2_rn(lo, hi);
    return *reinterpret_cast<uint32_t*>(&h);
}
__device__ __forceinline__ uint32_t smem_u32(const void* p) {
    uint32_t a;
    asm("{ .reg .u64 t; cvta.to.shared.u64 t, %1; cvt.u32.u64 %0, t; }" : "=r"(a) : "l"(p));
    return a;
}
__device__ __forceinline__ void mbar_init(uint32_t a, uint32_t cnt) {
    asm volatile("mbarrier.init.shared.b64 [%0], %1;" :: "r"(a), "r"(cnt) : "memory");
}
__device__ __forceinline__ void mbar_expect_tx(uint32_t a, uint32_t tx) {
    asm volatile("mbarrier.arrive.expect_tx.shared.b64 _, [%0], %1;" :: "r"(a), "r"(tx) : "memory");
}
__device__ __forceinline__ void mbar_arrive(uint32_t a) {
    asm volatile("mbarrier.arrive.shared.b64 _, [%0];" :: "r"(a) : "memory");
}
__device__ __forceinline__ void mbar_wait(uint32_t a, uint32_t parity) {
    asm volatile(
        "{\n\t.reg .pred P;\n\t"
        "W%=:\n\t"
        "mbarrier.try_wait.parity.shared.b64 P, [%0], %1;\n\t"
        "@!P bra W%=;\n\t}"
        :: "r"(a), "r"(parity) : "memory");
}
__device__ __forceinline__ void bulk_g2s(uint32_t dst, const void* src, uint32_t bytes, uint32_t mbar) {
    asm volatile(
        "cp.async.bulk.shared::cta.global.mbarrier::complete_tx::bytes [%0], [%1], %2, [%3];"
        :: "r"(dst), "l"(src), "r"(bytes), "r"(mbar) : "memory");
}

// ---------------------------------------------------------------------------
// Merged transform kernel: blocks [0,1024) do X, [1024,1536) do E.
// ---------------------------------------------------------------------------
__global__ void __launch_bounds__(256) transform_kernel(
    const float* __restrict__ xin, const float* __restrict__ eig) {
    if (blockIdx.x < 1024) {
        int t = blockIdx.x * 256 + threadIdx.x;   // 262144
        int lane = t & 31;
        int mt   = (t >> 5) & 7;
        int kt   = (t >> 8) & 31;
        int bmt  = t >> 13;
        int g = lane >> 2, tg = lane & 3;

        uint32_t regs[4][2][4];
        #pragma unroll
        for (int hi = 0; hi < 2; hi++) {
            int b = bmt * 128 + mt * 16 + g + 8 * hi;
            const float4* xr = reinterpret_cast<const float4*>(xin) + (size_t)b * GX;
            #pragma unroll
            for (int kstep = 0; kstep < 2; kstep++) {
                #pragma unroll
                for (int khi = 0; khi < 2; khi++) {
                    int xb = kt * 32 + kstep * 16 + khi * 8 + 2 * tg;
                    float4 f0 = xr[xb];
                    float4 f1 = xr[xb + 1];
                    float ue[4], uo[4];
                    ue[0] = f0.x + f0.y + f0.z + f0.w;  uo[0] = f1.x + f1.y + f1.z + f1.w;
                    ue[1] = f0.x - f0.z;                uo[1] = f1.x - f1.z;
                    ue[2] = f0.w - f0.y;                uo[2] = f1.w - f1.y;
                    ue[3] = f0.x - f0.y + f0.z - f0.w;  uo[3] = f1.x - f1.y + f1.z - f1.w;
                    int r = hi + 2 * khi;
                    #pragma unroll
                    for (int c = 0; c < 4; c++) regs[c][kstep][r] = pack_h2(ue[c], uo[c]);
                }
            }
        }
        uint32_t* tile = g_U + (size_t)(bmt * 32 + kt) * A_TILE_U32;
        #pragma unroll
        for (int c = 0; c < 4; c++)
            #pragma unroll
            for (int kstep = 0; kstep < 2; kstep++) {
                int idx = (((c * 8 + mt) * 2 + kstep) * 32 + lane) * 4;
                *reinterpret_cast<uint4*>(tile + idx) =
                    make_uint4(regs[c][kstep][0], regs[c][kstep][1],
                               regs[c][kstep][2], regs[c][kstep][3]);
            }
    } else {
        int t = (blockIdx.x - 1024) * 256 + threadIdx.x;   // 131072
        int lane = t & 31;
        int nt   = (t >> 5) & 7;
        int kt   = (t >> 8) & 31;
        int yt   = t >> 13;
        int g = lane >> 2, tg = lane & 3;

        int y = yt * 64 + nt * 8 + g;
        const float4* er = reinterpret_cast<const float4*>(eig) + (size_t)y * GX;

        uint32_t regs[5][2][2];
        #pragma unroll
        for (int kstep = 0; kstep < 2; kstep++) {
            #pragma unroll
            for (int khi = 0; khi < 2; khi++) {
                int xb = kt * 32 + kstep * 16 + khi * 8 + 2 * tg;
                float4 e0 = er[xb];
                float4 e1 = er[xb + 1];
                float pe[5], po[5];
                pe[0] = (e0.x + e0.y + e0.z + e0.w) * 0.25f;
                po[0] = (e1.x + e1.y + e1.z + e1.w) * 0.25f;
                pe[1] = (e0.x - e0.y + e0.z - e0.w) * 0.25f;
                po[1] = (e1.x - e1.y + e1.z - e1.w) * 0.25f;
                pe[2] = (e0.x - e0.z) * 0.5f;   po[2] = (e1.x - e1.z) * 0.5f;
                pe[3] = (e0.w - e0.y) * 0.5f;   po[3] = (e1.w - e1.y) * 0.5f;
                pe[4] = -pe[3];                 po[4] = -po[3];
                #pragma unroll
                for (int p = 0; p < 5; p++) regs[p][kstep][khi] = pack_h2(pe[p], po[p]);
            }
        }
        uint32_t* tile = g_E + (size_t)(yt * 32 + kt) * E_TILE_U32;
        #pragma unroll
        for (int p = 0; p < 5; p++)
            #pragma unroll
            for (int kstep = 0; kstep < 2; kstep++) {
                int idx = (((p * 4 + (nt >> 1)) * 2 + kstep) * 32 + lane) * 4 + (nt & 1) * 2;
                *reinterpret_cast<uint2*>(tile + idx) =
                    make_uint2(regs[p][kstep][0], regs[p][kstep][1]);
            }
    }
}

// ---------------------------------------------------------------------------
// GEMM: CTA owns 2 bmt x 2 yt sub-tiles. Per sub-tile 128b x 64 gy-blocks;
// 16 warps (8m x 2n), warp tile 16b x 32gy. 4-stage bulk+mbarrier ring.
// ---------------------------------------------------------------------------
#define STAGE_U32 (A_TILE_U32 + E_TILE_U32)       // 13312 (53248 B)
#define STAGES 4
#define HDR_U32 256                               // 1024 B header
#define SMEM_BYTES ((HDR_U32 + STAGES * STAGE_U32) * 4)   // 214016

__global__ void __launch_bounds__(512, 1) gemm_freq_kernel(float* __restrict__ out) {
    extern __shared__ uint32_t smem[];
    const uint32_t sbase  = smem_u32(smem);
    const uint32_t full0  = sbase;            // full[s]  at +8s
    const uint32_t empty0 = sbase + 32;       // empty[s] at +8s
    const uint32_t stage0 = sbase + HDR_U32 * 4;

    const int tid  = threadIdx.x;
    const int ytp  = blockIdx.x;   // 0..7
    const int bmtp = blockIdx.y;   // 0..15

    const int warp  = tid >> 5;
    const int lane  = tid & 31;
    const int g     = lane >> 2;
    const int tg    = lane & 3;
    const int warpM = warp & 7;    // 0..7 -> 16-row granule (mt index)
    const int warpN = warp >> 3;   // 0..1 -> 32-gy half

    if (tid == 0) {
        #pragma unroll
        for (int s = 0; s < STAGES; s++) {
            mbar_init(full0 + 8 * s, 1);
            mbar_init(empty0 + 8 * s, 16);
        }
    }
    __syncthreads();

    auto produce = [&](int gi) {
        int t2 = gi >> 5, kt2 = gi & 31;
        int bsel = t2 >> 1, ysel = bsel ^ (t2 & 1);
        const uint32_t* sA = g_U + (size_t)((bmtp * 2 + bsel) * 32 + kt2) * A_TILE_U32;
        const uint32_t* sE = g_E + (size_t)((ytp * 2 + ysel) * 32 + kt2) * E_TILE_U32;
        int s2 = gi & (STAGES - 1), r2 = gi >> 2;
        if (r2 >= 1) mbar_wait(empty0 + 8 * s2, (uint32_t)(r2 - 1) & 1u);
        uint32_t fb = full0 + 8 * s2;
        mbar_expect_tx(fb, STAGE_U32 * 4);
        uint32_t sa = stage0 + s2 * (STAGE_U32 * 4);
        bulk_g2s(sa, sA, A_TILE_U32 * 4, fb);
        bulk_g2s(sa + A_TILE_U32 * 4, sE, E_TILE_U32 * 4, fb);
    };

    if (tid == 0) { produce(0); produce(1); produce(2); }

    // Non-volatile MMA: ordering via data deps, ptxas may schedule freely.
    #define MMA(ACC, AF, B0, B1)                                                  \
        asm("mma.sync.aligned.m16n8k16.row.col.f32.f16.f16.f32 "                  \
            "{%0,%1,%2,%3}, {%4,%5,%6,%7}, {%8,%9}, {%0,%1,%2,%3};\n"             \
            : "+f"((ACC)[0]), "+f"((ACC)[1]), "+f"((ACC)[2]), "+f"((ACC)[3])      \
            : "r"((AF).x), "r"((AF).y), "r"((AF).z), "r"((AF).w),                 \
              "r"(B0), "r"(B1))

    for (int t = 0; t < 4; t++) {
        const int bsel = t >> 1, ysel = bsel ^ (t & 1);
        const int bm0  = (bmtp * 2 + bsel) * 128;
        const int bgy0 = (ytp * 2 + ysel) * 64;

        float acc[4][4][4];   // [set][ni][frag]  0=F0 1=F2 2=F1r 3=F1i
        #pragma unroll
        for (int s = 0; s < 4; s++)
            #pragma unroll
            for (int ni = 0; ni < 4; ni++)
                #pragma unroll
                for (int q = 0; q < 4; q++) acc[s][ni][q] = 0.0f;

        for (int kt = 0; kt < 32; kt++) {
            int gi = t * 32 + kt;
            if (tid == 0 && gi + 3 < 128) produce(gi + 3);

            int s = gi & (STAGES - 1);
            mbar_wait(full0 + 8 * s, (uint32_t)(gi >> 2) & 1u);

            const uint32_t* base = smem + HDR_U32 + s * STAGE_U32;
            const uint4* A4 = reinterpret_cast<const uint4*>(base);
            const uint4* E4 = reinterpret_cast<const uint4*>(base + A_TILE_U32);

            #pragma unroll
            for (int kstep = 0; kstep < 2; kstep++) {
                uint4 uf[4];
                #pragma unroll
                for (int c = 0; c < 4; c++)
                    uf[c] = A4[((c * 8 + warpM) * 2 + kstep) * 32 + lane];

                uint4 e4[5][2];
                #pragma unroll
                for (int p = 0; p < 5; p++)
                    #pragma unroll
                    for (int nip = 0; nip < 2; nip++)
                        e4[p][nip] = E4[((p * 4 + warpN * 2 + nip) * 2 + kstep) * 32 + lane];

                // slots: (accset, Acomp, Eplane)
                //  0:(0,u0,P0) 1:(1,u2,P2) 2:(2,u1r,P1r) 3:(3,u1r,P1i)
                //  4:(2,u1i,P1n) 5:(3,u1i,P1r)
                #pragma unroll
                for (int slot = 0; slot < 6; slot++) {
                    const int sset = (slot == 0) ? 0 : (slot == 1) ? 1
                                   : (slot == 2 || slot == 4) ? 2 : 3;
                    const int ac   = (slot == 0) ? 0 : (slot == 1) ? 3
                                   : (slot <= 3) ? 1 : 2;
                    const int ep   = (slot == 0) ? 0 : (slot == 1) ? 1
                                   : (slot == 2) ? 2 : (slot == 3) ? 3
                                   : (slot == 4) ? 4 : 2;
                    #pragma unroll
                    for (int ni = 0; ni < 4; ni++) {
                        const uint4& ev = e4[ep][ni >> 1];
                        uint32_t b0 = (ni & 1) ? ev.z : ev.x;
                        uint32_t b1 = (ni & 1) ? ev.w : ev.y;
                        MMA(acc[sset][ni], uf[ac], b0, b1);
                    }
                }
            }
            if (lane == 0) mbar_arrive(empty0 + 8 * s);
        }

        // Epilogue: inverse-DFT butterfly, float4 stores.
        #pragma unroll
        for (int ni = 0; ni < 4; ni++) {
            #pragma unroll
            for (int h = 0; h < 2; h++) {
                #pragma unroll
                for (int q = 0; q < 2; q++) {
                    int row = bm0 + warpM * 16 + g + h * 8;
                    int gy  = bgy0 + warpN * 32 + ni * 8 + 2 * tg + q;
                    float F0  = acc[0][ni][2 * h + q];
                    float F2  = acc[1][ni][2 * h + q];
                    float F1r = acc[2][ni][2 * h + q];
                    float F1i = acc[3][ni][2 * h + q];
                    float4 o;
                    o.x = F0 + F1r + F2;
                    o.y = F0 - F1i - F2;
                    o.z = F0 - F1r + F2;
                    o.w = F0 + F1i - F2;
                    *reinterpret_cast<float4*>(out + (size_t)row * N_DIM + 4 * gy) = o;
                }
            }
        }
    }
    #undef MMA
}

// ---------------------------------------------------------------------------
extern "C" void kernel_launch(void* const* d_in, const int* in_sizes, int n_in,
                              void* d_out, int out_size) {
    const float* x   = (const float*)d_in[0];   // (4096, 4096) f32
    const float* eig = (const float*)d_in[1];   // (1024, 1024, 4) f32
    float* out       = (float*)d_out;           // (4096, 4096) f32

    cudaFuncSetAttribute(gemm_freq_kernel,
                         cudaFuncAttributeMaxDynamicSharedMemorySize, SMEM_BYTES);

    transform_kernel<<<1536, 256>>>(x, eig);

    dim3 grid(8, 16);   // 128 CTAs, each 2 bmt x 2 yt sub-tiles => single wave
    gemm_freq_kernel<<<grid, 512, SMEM_BYTES>>>(out);
    (void)in_sizes; (void)n_in; (void)out_size;
}

// round 12
// speedup vs baseline: 1.2172x; 1.2172x over previous
#include <cuda_runtime.h>
#include <cuda_fp16.h>
#include <cstdint>

// Block-circulant linear via length-4 DFT diagonalization + Gauss 3-mult
// complex product (5/16 dense work). fp16 operands, f32 accumulation,
// fragment-order scratch, cp.async.bulk + mbarrier ring.
// R12 = R10 pipeline/tile structure + Gauss 5-slot math (now tensor-bound,
//       so trading MMAs for crossbar bytes pays, unlike R7's regime).
//
//   u0=a+b+c+d, u1r=a-c, u1i=d-b, u2=a-b+c-d, u1s=u1r+u1i   (per x block)
//   P0=Fe0/4, P2=Fe2/4, P1r=(e0-e2)/2, P1i=(e3-e1)/2, Pd=P1i-P1r, Ps=P1i+P1r
//   F0=sum P0*u0 ; F2=sum P2*u2 ; K1=sum P1r*u1s ; K2=sum Pd*u1r ; K3=sum Ps*u1i
//   F1r=K1-K3 ; F1i=K1+K2
//   o0=F0+F1r+F2  o1=F0-F1i-F2  o2=F0-F1r+F2  o3=F0+F1i-F2

#define B_DIM 4096
#define GX 1024
#define GY 1024
#define N_DIM 4096

// A tile (per bmt,kt): [c(5)][mt(8)][kstep(2)][lane(32)][reg(4)] f16x2 = 40KB
//   comp order: 0=u0, 1=u2, 2=u1s, 3=u1r, 4=u1i
// E tile (per yt, kt): [p(5)][ntp(4)][kstep(2)][lane(32)][4] f16x2 = 20KB
//   plane order: 0=P0, 1=P2, 2=P1r, 3=Pd, 4=Ps  (paired-nt layout)
#define A_TILE_U32 10240
#define E_TILE_U32 5120
__device__ uint32_t g_U[(size_t)32 * 32 * A_TILE_U32];   // 40 MB
__device__ uint32_t g_E[(size_t)16 * 32 * E_TILE_U32];   // 10 MB

__device__ __forceinline__ uint32_t pack_h2(float lo, float hi) {
    __half2 h = __floats2half2_rn(lo, hi);
    return *reinterpret_cast<uint32_t*>(&h);
}
__device__ __forceinline__ uint32_t smem_u32(const void* p) {
    uint32_t a;
    asm("{ .reg .u64 t; cvta.to.shared.u64 t, %1; cvt.u32.u64 %0, t; }" : "=r"(a) : "l"(p));
    return a;
}
__device__ __forceinline__ void mbar_init(uint32_t a, uint32_t cnt) {
    asm volatile("mbarrier.init.shared.b64 [%0], %1;" :: "r"(a), "r"(cnt) : "memory");
}
__device__ __forceinline__ void mbar_expect_tx(uint32_t a, uint32_t tx) {
    asm volatile("mbarrier.arrive.expect_tx.shared.b64 _, [%0], %1;" :: "r"(a), "r"(tx) : "memory");
}
__device__ __forceinline__ void mbar_arrive(uint32_t a) {
    asm volatile("mbarrier.arrive.shared.b64 _, [%0];" :: "r"(a) : "memory");
}
__device__ __forceinline__ void mbar_wait(uint32_t a, uint32_t parity) {
    asm volatile(
        "{\n\t.reg .pred P;\n\t"
        "W%=:\n\t"
        "mbarrier.try_wait.parity.shared.b64 P, [%0], %1;\n\t"
        "@!P bra W%=;\n\t}"
        :: "r"(a), "r"(parity) : "memory");
}
__device__ __forceinline__ void bulk_g2s(uint32_t dst, const void* src, uint32_t bytes, uint32_t mbar) {
    asm volatile(
        "cp.async.bulk.shared::cta.global.mbarrier::complete_tx::bytes [%0], [%1], %2, [%3];"
        :: "r"(dst), "l"(src), "r"(bytes), "r"(mbar) : "memory");
}

// ---------------------------------------------------------------------------
// Merged transform kernel: blocks [0,1024) do X, [1024,1536) do E.
// ---------------------------------------------------------------------------
__global__ void __launch_bounds__(256) transform_kernel(
    const float* __restrict__ xin, const float* __restrict__ eig) {
    if (blockIdx.x < 1024) {
        // ---- X path: thread = (bmt, kt, mt, lane); 5 fp16 A components ----
        int t = blockIdx.x * 256 + threadIdx.x;   // 262144
        int lane = t & 31;
        int mt   = (t >> 5) & 7;
        int kt   = (t >> 8) & 31;
        int bmt  = t >> 13;
        int g = lane >> 2, tg = lane & 3;

        uint32_t regs[5][2][4];
        #pragma unroll
        for (int hi = 0; hi < 2; hi++) {
            int b = bmt * 128 + mt * 16 + g + 8 * hi;
            const float4* xr = reinterpret_cast<const float4*>(xin) + (size_t)b * GX;
            #pragma unroll
            for (int kstep = 0; kstep < 2; kstep++) {
                #pragma unroll
                for (int khi = 0; khi < 2; khi++) {
                    int xb = kt * 32 + kstep * 16 + khi * 8 + 2 * tg;
                    float4 f0 = xr[xb];
                    float4 f1 = xr[xb + 1];
                    float e1r = f0.x - f0.z,  o1r = f1.x - f1.z;
                    float e1i = f0.w - f0.y,  o1i = f1.w - f1.y;
                    float ue[5], uo[5];
                    ue[0] = f0.x + f0.y + f0.z + f0.w;  uo[0] = f1.x + f1.y + f1.z + f1.w;
                    ue[1] = f0.x - f0.y + f0.z - f0.w;  uo[1] = f1.x - f1.y + f1.z - f1.w;
                    ue[2] = e1r + e1i;                  uo[2] = o1r + o1i;
                    ue[3] = e1r;                        uo[3] = o1r;
                    ue[4] = e1i;                        uo[4] = o1i;
                    int r = hi + 2 * khi;
                    #pragma unroll
                    for (int c = 0; c < 5; c++) regs[c][kstep][r] = pack_h2(ue[c], uo[c]);
                }
            }
        }
        uint32_t* tile = g_U + (size_t)(bmt * 32 + kt) * A_TILE_U32;
        #pragma unroll
        for (int c = 0; c < 5; c++)
            #pragma unroll
            for (int kstep = 0; kstep < 2; kstep++) {
                int idx = (((c * 8 + mt) * 2 + kstep) * 32 + lane) * 4;
                *reinterpret_cast<uint4*>(tile + idx) =
                    make_uint4(regs[c][kstep][0], regs[c][kstep][1],
                               regs[c][kstep][2], regs[c][kstep][3]);
            }
    } else {
        // ---- E path: thread = (yt, kt, nt, lane); 5 fp16 planes, paired ----
        int t = (blockIdx.x - 1024) * 256 + threadIdx.x;   // 131072
        int lane = t & 31;
        int nt   = (t >> 5) & 7;
        int kt   = (t >> 8) & 31;
        int yt   = t >> 13;
        int g = lane >> 2, tg = lane & 3;

        int y = yt * 64 + nt * 8 + g;
        const float4* er = reinterpret_cast<const float4*>(eig) + (size_t)y * GX;

        uint32_t regs[5][2][2];
        #pragma unroll
        for (int kstep = 0; kstep < 2; kstep++) {
            #pragma unroll
            for (int khi = 0; khi < 2; khi++) {
                int xb = kt * 32 + kstep * 16 + khi * 8 + 2 * tg;
                float4 e0 = er[xb];
                float4 e1 = er[xb + 1];
                float er0 = (e0.x - e0.z) * 0.5f,  or0 = (e1.x - e1.z) * 0.5f;   // P1r
                float ei0 = (e0.w - e0.y) * 0.5f,  oi0 = (e1.w - e1.y) * 0.5f;   // P1i
                float pe[5], po[5];
                pe[0] = (e0.x + e0.y + e0.z + e0.w) * 0.25f;
                po[0] = (e1.x + e1.y + e1.z + e1.w) * 0.25f;
                pe[1] = (e0.x - e0.y + e0.z - e0.w) * 0.25f;
                po[1] = (e1.x - e1.y + e1.z - e1.w) * 0.25f;
                pe[2] = er0;        po[2] = or0;
                pe[3] = ei0 - er0;  po[3] = oi0 - or0;
                pe[4] = ei0 + er0;  po[4] = oi0 + or0;
                #pragma unroll
                for (int p = 0; p < 5; p++) regs[p][kstep][khi] = pack_h2(pe[p], po[p]);
            }
        }
        uint32_t* tile = g_E + (size_t)(yt * 32 + kt) * E_TILE_U32;
        #pragma unroll
        for (int p = 0; p < 5; p++)
            #pragma unroll
            for (int kstep = 0; kstep < 2; kstep++) {
                int idx = (((p * 4 + (nt >> 1)) * 2 + kstep) * 32 + lane) * 4 + (nt & 1) * 2;
                *reinterpret_cast<uint2*>(tile + idx) =
                    make_uint2(regs[p][kstep][0], regs[p][kstep][1]);
            }
    }
}

// ---------------------------------------------------------------------------
// GEMM: CTA owns 2 bmt x 2 yt sub-tiles. Per sub-tile 128b x 64 gy-blocks;
// 8 warps (4m x 2n), warp 32b x 32gy. 3-stage bulk+mbarrier ring, depth 2.
// 5 uniform slots: acc[s] += A[s] * E[s].
// ---------------------------------------------------------------------------
#define STAGE_U32 (A_TILE_U32 + E_TILE_U32)       // 15360 (61440 B)
#define STAGES 3
#define HDR_U32 256                               // 1024 B header
#define SMEM_BYTES ((HDR_U32 + STAGES * STAGE_U32) * 4)   // 185344

__global__ void __launch_bounds__(256, 1) gemm_freq_kernel(float* __restrict__ out) {
    extern __shared__ uint32_t smem[];
    const uint32_t sbase  = smem_u32(smem);
    const uint32_t full0  = sbase;            // full[s]  at +8s
    const uint32_t empty0 = sbase + 32;       // empty[s] at +8s
    const uint32_t stage0 = sbase + HDR_U32 * 4;

    const int tid  = threadIdx.x;
    const int ytp  = blockIdx.x;   // 0..7
    const int bmtp = blockIdx.y;   // 0..15

    const int warp  = tid >> 5;
    const int lane  = tid & 31;
    const int g     = lane >> 2;
    const int tg    = lane & 3;
    const int warpM = warp & 3;
    const int warpN = warp >> 2;

    if (tid == 0) {
        #pragma unroll
        for (int s = 0; s < STAGES; s++) {
            mbar_init(full0 + 8 * s, 1);
            mbar_init(empty0 + 8 * s, 8);
        }
    }
    __syncthreads();

    auto produce = [&](int gi) {
        int t2 = gi >> 5, kt2 = gi & 31;
        int bsel = t2 >> 1, ysel = bsel ^ (t2 & 1);
        const uint32_t* sA = g_U + (size_t)((bmtp * 2 + bsel) * 32 + kt2) * A_TILE_U32;
        const uint32_t* sE = g_E + (size_t)((ytp * 2 + ysel) * 32 + kt2) * E_TILE_U32;
        int s2 = gi % 3, r2 = gi / 3;
        if (r2 >= 1) mbar_wait(empty0 + 8 * s2, (uint32_t)(r2 - 1) & 1u);
        uint32_t fb = full0 + 8 * s2;
        mbar_expect_tx(fb, STAGE_U32 * 4);
        uint32_t sa = stage0 + s2 * (STAGE_U32 * 4);
        bulk_g2s(sa, sA, A_TILE_U32 * 4, fb);
        bulk_g2s(sa + A_TILE_U32 * 4, sE, E_TILE_U32 * 4, fb);
    };

    if (tid == 0) { produce(0); produce(1); }

    // Non-volatile MMA: ordering via data deps, ptxas may schedule freely.
    #define MMA(ACC, AF, B0, B1)                                                  \
        asm("mma.sync.aligned.m16n8k16.row.col.f32.f16.f16.f32 "                  \
            "{%0,%1,%2,%3}, {%4,%5,%6,%7}, {%8,%9}, {%0,%1,%2,%3};\n"             \
            : "+f"((ACC)[0]), "+f"((ACC)[1]), "+f"((ACC)[2]), "+f"((ACC)[3])      \
            : "r"((AF).x), "r"((AF).y), "r"((AF).z), "r"((AF).w),                 \
              "r"(B0), "r"(B1))

    for (int t = 0; t < 4; t++) {
        const int bsel = t >> 1, ysel = bsel ^ (t & 1);
        const int bm0  = (bmtp * 2 + bsel) * 128;
        const int bgy0 = (ytp * 2 + ysel) * 64;

        // acc sets: 0=F0, 1=F2, 2=K1, 3=K2, 4=K3
        float acc[5][2][4][4];
        #pragma unroll
        for (int s = 0; s < 5; s++)
            #pragma unroll
            for (int mi = 0; mi < 2; mi++)
                #pragma unroll
                for (int ni = 0; ni < 4; ni++)
                    #pragma unroll
                    for (int q = 0; q < 4; q++) acc[s][mi][ni][q] = 0.0f;

        for (int kt = 0; kt < 32; kt++) {
            int gi = t * 32 + kt;
            if (tid == 0 && gi + 2 < 128) produce(gi + 2);

            int s = gi % 3;
            mbar_wait(full0 + 8 * s, (uint32_t)(gi / 3) & 1u);

            const uint32_t* base = smem + HDR_U32 + s * STAGE_U32;
            const uint4* A4 = reinterpret_cast<const uint4*>(base);
            const uint4* E4 = reinterpret_cast<const uint4*>(base + A_TILE_U32);

            #pragma unroll
            for (int kstep = 0; kstep < 2; kstep++) {
                uint4 uf[5][2];
                #pragma unroll
                for (int c = 0; c < 5; c++)
                    #pragma unroll
                    for (int mi = 0; mi < 2; mi++)
                        uf[c][mi] = A4[((c * 8 + warpM * 2 + mi) * 2 + kstep) * 32 + lane];

                // Uniform slots: acc[s] += A[s] * E[s]
                #pragma unroll
                for (int p = 0; p < 5; p++) {
                    #pragma unroll
                    for (int nip = 0; nip < 2; nip++) {
                        uint4 e4 = E4[((p * 4 + warpN * 2 + nip) * 2 + kstep) * 32 + lane];
                        #pragma unroll
                        for (int half = 0; half < 2; half++) {
                            int ni = 2 * nip + half;
                            uint32_t b0 = half ? e4.z : e4.x;
                            uint32_t b1 = half ? e4.w : e4.y;
                            #pragma unroll
                            for (int mi = 0; mi < 2; mi++)
                                MMA(acc[p][mi][ni], uf[p][mi], b0, b1);
                        }
                    }
                }
            }
            if (lane == 0) mbar_arrive(empty0 + 8 * s);
        }

        // Epilogue: Gauss recombine + inverse-DFT butterfly.
        #pragma unroll
        for (int mi = 0; mi < 2; mi++) {
            #pragma unroll
            for (int ni = 0; ni < 4; ni++) {
                #pragma unroll
                for (int h = 0; h < 2; h++) {
                    #pragma unroll
                    for (int q = 0; q < 2; q++) {
                        int row = bm0 + warpM * 32 + mi * 16 + g + h * 8;
                        int gy  = bgy0 + warpN * 32 + ni * 8 + 2 * tg + q;
                        float F0 = acc[0][mi][ni][2 * h + q];
                        float F2 = acc[1][mi][ni][2 * h + q];
                        float K1 = acc[2][mi][ni][2 * h + q];
                        float K2 = acc[3][mi][ni][2 * h + q];
                        float K3 = acc[4][mi][ni][2 * h + q];
                        float F1r = K1 - K3;
                        float F1i = K1 + K2;
                        float4 o;
                        o.x = F0 + F1r + F2;
                        o.y = F0 - F1i - F2;
                        o.z = F0 - F1r + F2;
                        o.w = F0 + F1i - F2;
                        *reinterpret_cast<float4*>(out + (size_t)row * N_DIM + 4 * gy) = o;
                    }
                }
            }
        }
    }
    #undef MMA
}

// ---------------------------------------------------------------------------
extern "C" void kernel_launch(void* const* d_in, const int* in_sizes, int n_in,
                              void* d_out, int out_size) {
    const float* x   = (const float*)d_in[0];   // (4096, 4096) f32
    const float* eig = (const float*)d_in[1];   // (1024, 1024, 4) f32
    float* out       = (float*)d_out;           // (4096, 4096) f32

    cudaFuncSetAttribute(gemm_freq_kernel,
                         cudaFuncAttributeMaxDynamicSharedMemorySize, SMEM_BYTES);

    transform_kernel<<<1536, 256>>>(x, eig);

    dim3 grid(8, 16);   // 128 CTAs, each 2 bmt x 2 yt sub-tiles => single wave
    gemm_freq_kernel<<<grid, 256, SMEM_BYTES>>>(out);
    (void)in_sizes; (void)n_in; (void)out_size;
}

// round 14
// speedup vs baseline: 1.2200x; 1.0023x over previous
#include <cuda_runtime.h>
#include <cuda_fp16.h>
#include <cstdint>

// Block-circulant linear via length-4 DFT diagonalization + Gauss 3-mult
// complex product (5/16 dense work). fp16 operands, f32 accumulation.
// R13b: derived operands (u1s, Pd, Ps) computed in-register with HADD2/HSUB2
//       instead of stored -> crossbar 220->176 KB/kt; 4-stage ring.
//       (fix: no #pragma inside macro body)
//
//   u0=a+b+c+d, u1r=a-c, u1i=d-b, u2=a-b+c-d   (per x block)
//   P0=Fe0/4, P2=Fe2/4, P1r=(e0-e2)/2, P1i=(e3-e1)/2
//   u1s=u1r+u1i, Pd=P1i-P1r, Ps=P1i+P1r      (derived in-kernel)
//   F0=sum P0*u0 ; F2=sum P2*u2 ; K1=sum P1r*u1s ; K2=sum Pd*u1r ; K3=sum Ps*u1i
//   F1r=K1-K3 ; F1i=K1+K2
//   o0=F0+F1r+F2  o1=F0-F1i-F2  o2=F0-F1r+F2  o3=F0+F1i-F2

#define B_DIM 4096
#define GX 1024
#define GY 1024
#define N_DIM 4096

// A tile (per bmt,kt): [c(4)][mt(8)][kstep(2)][lane(32)][reg(4)] f16x2 = 32KB
//   comp order: 0=u0, 1=u2, 2=u1r, 3=u1i
// E tile (per yt, kt): [p(4)][ntp(4)][kstep(2)][lane(32)][4] f16x2 = 16KB
//   plane order: 0=P0, 1=P2, 2=P1r, 3=P1i  (paired-nt layout)
#define A_TILE_U32 8192
#define E_TILE_U32 4096
__device__ uint32_t g_U[(size_t)32 * 32 * A_TILE_U32];   // 32 MB
__device__ uint32_t g_E[(size_t)16 * 32 * E_TILE_U32];   // 8 MB

__device__ __forceinline__ uint32_t pack_h2(float lo, float hi) {
    __half2 h = __floats2half2_rn(lo, hi);
    return *reinterpret_cast<uint32_t*>(&h);
}
__device__ __forceinline__ uint32_t hadd2u(uint32_t a, uint32_t b) {
    __half2 r = __hadd2(*reinterpret_cast<__half2*>(&a), *reinterpret_cast<__half2*>(&b));
    return *reinterpret_cast<uint32_t*>(&r);
}
__device__ __forceinline__ uint32_t hsub2u(uint32_t a, uint32_t b) {
    __half2 r = __hsub2(*reinterpret_cast<__half2*>(&a), *reinterpret_cast<__half2*>(&b));
    return *reinterpret_cast<uint32_t*>(&r);
}
__device__ __forceinline__ uint4 hadd2u4(uint4 a, uint4 b) {
    return make_uint4(hadd2u(a.x, b.x), hadd2u(a.y, b.y),
                      hadd2u(a.z, b.z), hadd2u(a.w, b.w));
}
__device__ __forceinline__ uint4 hsub2u4(uint4 a, uint4 b) {
    return make_uint4(hsub2u(a.x, b.x), hsub2u(a.y, b.y),
                      hsub2u(a.z, b.z), hsub2u(a.w, b.w));
}
__device__ __forceinline__ uint32_t smem_u32(const void* p) {
    uint32_t a;
    asm("{ .reg .u64 t; cvta.to.shared.u64 t, %1; cvt.u32.u64 %0, t; }" : "=r"(a) : "l"(p));
    return a;
}
__device__ __forceinline__ void mbar_init(uint32_t a, uint32_t cnt) {
    asm volatile("mbarrier.init.shared.b64 [%0], %1;" :: "r"(a), "r"(cnt) : "memory");
}
__device__ __forceinline__ void mbar_expect_tx(uint32_t a, uint32_t tx) {
    asm volatile("mbarrier.arrive.expect_tx.shared.b64 _, [%0], %1;" :: "r"(a), "r"(tx) : "memory");
}
__device__ __forceinline__ void mbar_arrive(uint32_t a) {
    asm volatile("mbarrier.arrive.shared.b64 _, [%0];" :: "r"(a) : "memory");
}
__device__ __forceinline__ void mbar_wait(uint32_t a, uint32_t parity) {
    asm volatile(
        "{\n\t.reg .pred P;\n\t"
        "W%=:\n\t"
        "mbarrier.try_wait.parity.shared.b64 P, [%0], %1;\n\t"
        "@!P bra W%=;\n\t}"
        :: "r"(a), "r"(parity) : "memory");
}
__device__ __forceinline__ void bulk_g2s(uint32_t dst, const void* src, uint32_t bytes, uint32_t mbar) {
    asm volatile(
        "cp.async.bulk.shared::cta.global.mbarrier::complete_tx::bytes [%0], [%1], %2, [%3];"
        :: "r"(dst), "l"(src), "r"(bytes), "r"(mbar) : "memory");
}

// ---------------------------------------------------------------------------
// Merged transform kernel: blocks [0,1024) do X, [1024,1536) do E.
// ---------------------------------------------------------------------------
__global__ void __launch_bounds__(256) transform_kernel(
    const float* __restrict__ xin, const float* __restrict__ eig) {
    if (blockIdx.x < 1024) {
        // ---- X path: thread = (bmt, kt, mt, lane); 4 fp16 A components ----
        int t = blockIdx.x * 256 + threadIdx.x;   // 262144
        int lane = t & 31;
        int mt   = (t >> 5) & 7;
        int kt   = (t >> 8) & 31;
        int bmt  = t >> 13;
        int g = lane >> 2, tg = lane & 3;

        uint32_t regs[4][2][4];
        #pragma unroll
        for (int hi = 0; hi < 2; hi++) {
            int b = bmt * 128 + mt * 16 + g + 8 * hi;
            const float4* xr = reinterpret_cast<const float4*>(xin) + (size_t)b * GX;
            #pragma unroll
            for (int kstep = 0; kstep < 2; kstep++) {
                #pragma unroll
                for (int khi = 0; khi < 2; khi++) {
                    int xb = kt * 32 + kstep * 16 + khi * 8 + 2 * tg;
                    float4 f0 = xr[xb];
                    float4 f1 = xr[xb + 1];
                    float ue[4], uo[4];
                    ue[0] = f0.x + f0.y + f0.z + f0.w;  uo[0] = f1.x + f1.y + f1.z + f1.w;
                    ue[1] = f0.x - f0.y + f0.z - f0.w;  uo[1] = f1.x - f1.y + f1.z - f1.w;
                    ue[2] = f0.x - f0.z;                uo[2] = f1.x - f1.z;
                    ue[3] = f0.w - f0.y;                uo[3] = f1.w - f1.y;
                    int r = hi + 2 * khi;
                    #pragma unroll
                    for (int c = 0; c < 4; c++) regs[c][kstep][r] = pack_h2(ue[c], uo[c]);
                }
            }
        }
        uint32_t* tile = g_U + (size_t)(bmt * 32 + kt) * A_TILE_U32;
        #pragma unroll
        for (int c = 0; c < 4; c++)
            #pragma unroll
            for (int kstep = 0; kstep < 2; kstep++) {
                int idx = (((c * 8 + mt) * 2 + kstep) * 32 + lane) * 4;
                *reinterpret_cast<uint4*>(tile + idx) =
                    make_uint4(regs[c][kstep][0], regs[c][kstep][1],
                               regs[c][kstep][2], regs[c][kstep][3]);
            }
    } else {
        // ---- E path: thread = (yt, kt, nt, lane); 4 fp16 planes, paired ----
        int t = (blockIdx.x - 1024) * 256 + threadIdx.x;   // 131072
        int lane = t & 31;
        int nt   = (t >> 5) & 7;
        int kt   = (t >> 8) & 31;
        int yt   = t >> 13;
        int g = lane >> 2, tg = lane & 3;

        int y = yt * 64 + nt * 8 + g;
        const float4* er = reinterpret_cast<const float4*>(eig) + (size_t)y * GX;

        uint32_t regs[4][2][2];
        #pragma unroll
        for (int kstep = 0; kstep < 2; kstep++) {
            #pragma unroll
            for (int khi = 0; khi < 2; khi++) {
                int xb = kt * 32 + kstep * 16 + khi * 8 + 2 * tg;
                float4 e0 = er[xb];
                float4 e1 = er[xb + 1];
                float pe[4], po[4];
                pe[0] = (e0.x + e0.y + e0.z + e0.w) * 0.25f;
                po[0] = (e1.x + e1.y + e1.z + e1.w) * 0.25f;
                pe[1] = (e0.x - e0.y + e0.z - e0.w) * 0.25f;
                po[1] = (e1.x - e1.y + e1.z - e1.w) * 0.25f;
                pe[2] = (e0.x - e0.z) * 0.5f;   po[2] = (e1.x - e1.z) * 0.5f;   // P1r
                pe[3] = (e0.w - e0.y) * 0.5f;   po[3] = (e1.w - e1.y) * 0.5f;   // P1i
                #pragma unroll
                for (int p = 0; p < 4; p++) regs[p][kstep][khi] = pack_h2(pe[p], po[p]);
            }
        }
        uint32_t* tile = g_E + (size_t)(yt * 32 + kt) * E_TILE_U32;
        #pragma unroll
        for (int p = 0; p < 4; p++)
            #pragma unroll
            for (int kstep = 0; kstep < 2; kstep++) {
                int idx = (((p * 4 + (nt >> 1)) * 2 + kstep) * 32 + lane) * 4 + (nt & 1) * 2;
                *reinterpret_cast<uint2*>(tile + idx) =
                    make_uint2(regs[p][kstep][0], regs[p][kstep][1]);
            }
    }
}

// ---------------------------------------------------------------------------
// GEMM: CTA owns 2 bmt x 2 yt sub-tiles. Per sub-tile 128b x 64 gy-blocks;
// 8 warps (4m x 2n), warp 32b x 32gy. 4-stage bulk+mbarrier ring, depth 3.
// Gauss 5 slots with derived operands computed in-register.
// ---------------------------------------------------------------------------
#define STAGE_U32 (A_TILE_U32 + E_TILE_U32)       // 12288 (49152 B)
#define STAGES 4
#define HDR_U32 256                               // 1024 B header
#define SMEM_BYTES ((HDR_U32 + STAGES * STAGE_U32) * 4)   // 197632

__global__ void __launch_bounds__(256, 1) gemm_freq_kernel(float* __restrict__ out) {
    extern __shared__ uint32_t smem[];
    const uint32_t sbase  = smem_u32(smem);
    const uint32_t full0  = sbase;            // full[s]  at +8s
    const uint32_t empty0 = sbase + 32;       // empty[s] at +8s
    const uint32_t stage0 = sbase + HDR_U32 * 4;

    const int tid  = threadIdx.x;
    const int ytp  = blockIdx.x;   // 0..7
    const int bmtp = blockIdx.y;   // 0..15

    const int warp  = tid >> 5;
    const int lane  = tid & 31;
    const int g     = lane >> 2;
    const int tg    = lane & 3;
    const int warpM = warp & 3;
    const int warpN = warp >> 2;

    if (tid == 0) {
        #pragma unroll
        for (int s = 0; s < STAGES; s++) {
            mbar_init(full0 + 8 * s, 1);
            mbar_init(empty0 + 8 * s, 8);
        }
    }
    __syncthreads();

    auto produce = [&](int gi) {
        int t2 = gi >> 5, kt2 = gi & 31;
        int bsel = t2 >> 1, ysel = bsel ^ (t2 & 1);
        const uint32_t* sA = g_U + (size_t)((bmtp * 2 + bsel) * 32 + kt2) * A_TILE_U32;
        const uint32_t* sE = g_E + (size_t)((ytp * 2 + ysel) * 32 + kt2) * E_TILE_U32;
        int s2 = gi & (STAGES - 1), r2 = gi >> 2;
        if (r2 >= 1) mbar_wait(empty0 + 8 * s2, (uint32_t)(r2 - 1) & 1u);
        uint32_t fb = full0 + 8 * s2;
        mbar_expect_tx(fb, STAGE_U32 * 4);
        uint32_t sa = stage0 + s2 * (STAGE_U32 * 4);
        bulk_g2s(sa, sA, A_TILE_U32 * 4, fb);
        bulk_g2s(sa + A_TILE_U32 * 4, sE, E_TILE_U32 * 4, fb);
    };

    if (tid == 0) { produce(0); produce(1); produce(2); }

    // Non-volatile MMA: ordering via data deps, ptxas may schedule freely.
    #define MMA(ACC, AF, B0, B1)                                                  \
        asm("mma.sync.aligned.m16n8k16.row.col.f32.f16.f16.f32 "                  \
            "{%0,%1,%2,%3}, {%4,%5,%6,%7}, {%8,%9}, {%0,%1,%2,%3};\n"             \
            : "+f"((ACC)[0]), "+f"((ACC)[1]), "+f"((ACC)[2]), "+f"((ACC)[3])      \
            : "r"((AF).x), "r"((AF).y), "r"((AF).z), "r"((AF).w),                 \
              "r"(B0), "r"(B1))

    // manual mi-unroll (no #pragma inside macro bodies!)
    #define MMA4(ACCSET, AF, EV0, EV1)                                            \
        do {                                                                      \
            MMA(acc[ACCSET][0][0], (AF)[0], (EV0).x, (EV0).y);                    \
            MMA(acc[ACCSET][0][1], (AF)[0], (EV0).z, (EV0).w);                    \
            MMA(acc[ACCSET][0][2], (AF)[0], (EV1).x, (EV1).y);                    \
            MMA(acc[ACCSET][0][3], (AF)[0], (EV1).z, (EV1).w);                    \
            MMA(acc[ACCSET][1][0], (AF)[1], (EV0).x, (EV0).y);                    \
            MMA(acc[ACCSET][1][1], (AF)[1], (EV0).z, (EV0).w);                    \
            MMA(acc[ACCSET][1][2], (AF)[1], (EV1).x, (EV1).y);                    \
            MMA(acc[ACCSET][1][3], (AF)[1], (EV1).z, (EV1).w);                    \
        } while (0)

    for (int t = 0; t < 4; t++) {
        const int bsel = t >> 1, ysel = bsel ^ (t & 1);
        const int bm0  = (bmtp * 2 + bsel) * 128;
        const int bgy0 = (ytp * 2 + ysel) * 64;

        // acc sets: 0=F0, 1=F2, 2=K1, 3=K2, 4=K3
        float acc[5][2][4][4];
        #pragma unroll
        for (int s = 0; s < 5; s++)
            #pragma unroll
            for (int mi = 0; mi < 2; mi++)
                #pragma unroll
                for (int ni = 0; ni < 4; ni++)
                    #pragma unroll
                    for (int q = 0; q < 4; q++) acc[s][mi][ni][q] = 0.0f;

        for (int kt = 0; kt < 32; kt++) {
            int gi = t * 32 + kt;
            if (tid == 0 && gi + 3 < 128) produce(gi + 3);

            int s = gi & (STAGES - 1);
            mbar_wait(full0 + 8 * s, (uint32_t)(gi >> 2) & 1u);

            const uint32_t* base = smem + HDR_U32 + s * STAGE_U32;
            const uint4* A4 = reinterpret_cast<const uint4*>(base);
            const uint4* E4 = reinterpret_cast<const uint4*>(base + A_TILE_U32);

            #pragma unroll
            for (int kstep = 0; kstep < 2; kstep++) {
                // A comps: 0=u0, 1=u2, 2=u1r, 3=u1i
                uint4 uf[4][2];
                #pragma unroll
                for (int c = 0; c < 4; c++)
                    #pragma unroll
                    for (int mi = 0; mi < 2; mi++)
                        uf[c][mi] = A4[((c * 8 + warpM * 2 + mi) * 2 + kstep) * 32 + lane];
                // derived u1s = u1r + u1i
                uint4 us[2];
                us[0] = hadd2u4(uf[2][0], uf[3][0]);
                us[1] = hadd2u4(uf[2][1], uf[3][1]);

                // E planes paired: p index, nip in {0,1}
                #define ELOAD(p, nip) E4[(((p) * 4 + warpN * 2 + (nip)) * 2 + kstep) * 32 + lane]

                // slot F0: P0 * u0
                {
                    uint4 e0 = ELOAD(0, 0), e1 = ELOAD(0, 1);
                    MMA4(0, uf[0], e0, e1);
                }
                // slot F2: P2 * u2
                {
                    uint4 e0 = ELOAD(1, 0), e1 = ELOAD(1, 1);
                    MMA4(1, uf[1], e0, e1);
                }
                // load P1r, P1i
                uint4 r0 = ELOAD(2, 0), r1 = ELOAD(2, 1);
                uint4 i0 = ELOAD(3, 0), i1 = ELOAD(3, 1);
                #undef ELOAD
                // slot K1: P1r * u1s
                MMA4(2, us, r0, r1);
                // slot K2: Pd * u1r,  Pd = P1i - P1r
                {
                    uint4 d0 = hsub2u4(i0, r0);
                    uint4 d1 = hsub2u4(i1, r1);
                    MMA4(3, uf[2], d0, d1);
                }
                // slot K3: Ps * u1i,  Ps = P1i + P1r
                {
                    uint4 s0 = hadd2u4(i0, r0);
                    uint4 s1 = hadd2u4(i1, r1);
                    MMA4(4, uf[3], s0, s1);
                }
            }
            if (lane == 0) mbar_arrive(empty0 + 8 * s);
        }

        // Epilogue: Gauss recombine + inverse-DFT butterfly.
        #pragma unroll
        for (int mi = 0; mi < 2; mi++) {
            #pragma unroll
            for (int ni = 0; ni < 4; ni++) {
                #pragma unroll
                for (int h = 0; h < 2; h++) {
                    #pragma unroll
                    for (int q = 0; q < 2; q++) {
                        int row = bm0 + warpM * 32 + mi * 16 + g + h * 8;
                        int gy  = bgy0 + warpN * 32 + ni * 8 + 2 * tg + q;
                        float F0 = acc[0][mi][ni][2 * h + q];
                        float F2 = acc[1][mi][ni][2 * h + q];
                        float K1 = acc[2][mi][ni][2 * h + q];
                        float K2 = acc[3][mi][ni][2 * h + q];
                        float K3 = acc[4][mi][ni][2 * h + q];
                        float F1r = K1 - K3;
                        float F1i = K1 + K2;
                        float4 o;
                        o.x = F0 + F1r + F2;
                        o.y = F0 - F1i - F2;
                        o.z = F0 - F1r + F2;
                        o.w = F0 + F1i - F2;
                        *reinterpret_cast<float4*>(out + (size_t)row * N_DIM + 4 * gy) = o;
                    }
                }
            }
        }
    }
    #undef MMA4
    #undef MMA
}

// ---------------------------------------------------------------------------
extern "C" void kernel_launch(void* const* d_in, const int* in_sizes, int n_in,
                              void* d_out, int out_size) {
    const float* x   = (const float*)d_in[0];   // (4096, 4096) f32
    const float* eig = (const float*)d_in[1];   // (1024, 1024, 4) f32
    float* out       = (float*)d_out;           // (4096, 4096) f32

    cudaFuncSetAttribute(gemm_freq_kernel,
                         cudaFuncAttributeMaxDynamicSharedMemorySize, SMEM_BYTES);

    transform_kernel<<<1536, 256>>>(x, eig);

    dim3 grid(8, 16);   // 128 CTAs, each 2 bmt x 2 yt sub-tiles => single wave
    gemm_freq_kernel<<<grid, 256, SMEM_BYTES>>>(out);
    (void)in_sizes; (void)n_in; (void)out_size;
}

// round 15
// speedup vs baseline: 1.2393x; 1.0158x over previous
#include <cuda_runtime.h>
#include <cuda_fp16.h>
#include <cstdint>

// Block-circulant linear via length-4 DFT diagonalization + Gauss 3-mult
// complex product (5/16 dense work). fp16 operands, f32 accumulation.
// R15: paired-stage consumption — one mbar wait + one unbroken 320-MMA run
//      per 2 kt, halving per-kt pipeline sync exposure. R14 math/layouts.
//
//   u0=a+b+c+d, u1r=a-c, u1i=d-b, u2=a-b+c-d   (per x block)
//   P0=Fe0/4, P2=Fe2/4, P1r=(e0-e2)/2, P1i=(e3-e1)/2
//   u1s=u1r+u1i, Pd=P1i-P1r, Ps=P1i+P1r      (derived in-kernel)
//   F0=sum P0*u0 ; F2=sum P2*u2 ; K1=sum P1r*u1s ; K2=sum Pd*u1r ; K3=sum Ps*u1i
//   F1r=K1-K3 ; F1i=K1+K2
//   o0=F0+F1r+F2  o1=F0-F1i-F2  o2=F0-F1r+F2  o3=F0+F1i-F2

#define B_DIM 4096
#define GX 1024
#define GY 1024
#define N_DIM 4096

// A tile (per bmt,kt): [c(4)][mt(8)][kstep(2)][lane(32)][reg(4)] f16x2 = 32KB
//   comp order: 0=u0, 1=u2, 2=u1r, 3=u1i
// E tile (per yt, kt): [p(4)][ntp(4)][kstep(2)][lane(32)][4] f16x2 = 16KB
//   plane order: 0=P0, 1=P2, 2=P1r, 3=P1i  (paired-nt layout)
#define A_TILE_U32 8192
#define E_TILE_U32 4096
__device__ uint32_t g_U[(size_t)32 * 32 * A_TILE_U32];   // 32 MB
__device__ uint32_t g_E[(size_t)16 * 32 * E_TILE_U32];   // 8 MB

__device__ __forceinline__ uint32_t pack_h2(float lo, float hi) {
    __half2 h = __floats2half2_rn(lo, hi);
    return *reinterpret_cast<uint32_t*>(&h);
}
__device__ __forceinline__ uint32_t hadd2u(uint32_t a, uint32_t b) {
    __half2 r = __hadd2(*reinterpret_cast<__half2*>(&a), *reinterpret_cast<__half2*>(&b));
    return *reinterpret_cast<uint32_t*>(&r);
}
__device__ __forceinline__ uint32_t hsub2u(uint32_t a, uint32_t b) {
    __half2 r = __hsub2(*reinterpret_cast<__half2*>(&a), *reinterpret_cast<__half2*>(&b));
    return *reinterpret_cast<uint32_t*>(&r);
}
__device__ __forceinline__ uint4 hadd2u4(uint4 a, uint4 b) {
    return make_uint4(hadd2u(a.x, b.x), hadd2u(a.y, b.y),
                      hadd2u(a.z, b.z), hadd2u(a.w, b.w));
}
__device__ __forceinline__ uint4 hsub2u4(uint4 a, uint4 b) {
    return make_uint4(hsub2u(a.x, b.x), hsub2u(a.y, b.y),
                      hsub2u(a.z, b.z), hsub2u(a.w, b.w));
}
__device__ __forceinline__ uint32_t smem_u32(const void* p) {
    uint32_t a;
    asm("{ .reg .u64 t; cvta.to.shared.u64 t, %1; cvt.u32.u64 %0, t; }" : "=r"(a) : "l"(p));
    return a;
}
__device__ __forceinline__ void mbar_init(uint32_t a, uint32_t cnt) {
    asm volatile("mbarrier.init.shared.b64 [%0], %1;" :: "r"(a), "r"(cnt) : "memory");
}
__device__ __forceinline__ void mbar_expect_tx(uint32_t a, uint32_t tx) {
    asm volatile("mbarrier.arrive.expect_tx.shared.b64 _, [%0], %1;" :: "r"(a), "r"(tx) : "memory");
}
__device__ __forceinline__ void mbar_arrive(uint32_t a) {
    asm volatile("mbarrier.arrive.shared.b64 _, [%0];" :: "r"(a) : "memory");
}
__device__ __forceinline__ void mbar_wait(uint32_t a, uint32_t parity) {
    asm volatile(
        "{\n\t.reg .pred P;\n\t"
        "W%=:\n\t"
        "mbarrier.try_wait.parity.shared.b64 P, [%0], %1;\n\t"
        "@!P bra W%=;\n\t}"
        :: "r"(a), "r"(parity) : "memory");
}
__device__ __forceinline__ void bulk_g2s(uint32_t dst, const void* src, uint32_t bytes, uint32_t mbar) {
    asm volatile(
        "cp.async.bulk.shared::cta.global.mbarrier::complete_tx::bytes [%0], [%1], %2, [%3];"
        :: "r"(dst), "l"(src), "r"(bytes), "r"(mbar) : "memory");
}

// ---------------------------------------------------------------------------
// Merged transform kernel: blocks [0,1024) do X, [1024,1536) do E.
// ---------------------------------------------------------------------------
__global__ void __launch_bounds__(256) transform_kernel(
    const float* __restrict__ xin, const float* __restrict__ eig) {
    if (blockIdx.x < 1024) {
        // ---- X path: thread = (bmt, kt, mt, lane); 4 fp16 A components ----
        int t = blockIdx.x * 256 + threadIdx.x;   // 262144
        int lane = t & 31;
        int mt   = (t >> 5) & 7;
        int kt   = (t >> 8) & 31;
        int bmt  = t >> 13;
        int g = lane >> 2, tg = lane & 3;

        uint32_t regs[4][2][4];
        #pragma unroll
        for (int hi = 0; hi < 2; hi++) {
            int b = bmt * 128 + mt * 16 + g + 8 * hi;
            const float4* xr = reinterpret_cast<const float4*>(xin) + (size_t)b * GX;
            #pragma unroll
            for (int kstep = 0; kstep < 2; kstep++) {
                #pragma unroll
                for (int khi = 0; khi < 2; khi++) {
                    int xb = kt * 32 + kstep * 16 + khi * 8 + 2 * tg;
                    float4 f0 = xr[xb];
                    float4 f1 = xr[xb + 1];
                    float ue[4], uo[4];
                    ue[0] = f0.x + f0.y + f0.z + f0.w;  uo[0] = f1.x + f1.y + f1.z + f1.w;
                    ue[1] = f0.x - f0.y + f0.z - f0.w;  uo[1] = f1.x - f1.y + f1.z - f1.w;
                    ue[2] = f0.x - f0.z;                uo[2] = f1.x - f1.z;
                    ue[3] = f0.w - f0.y;                uo[3] = f1.w - f1.y;
                    int r = hi + 2 * khi;
                    #pragma unroll
                    for (int c = 0; c < 4; c++) regs[c][kstep][r] = pack_h2(ue[c], uo[c]);
                }
            }
        }
        uint32_t* tile = g_U + (size_t)(bmt * 32 + kt) * A_TILE_U32;
        #pragma unroll
        for (int c = 0; c < 4; c++)
            #pragma unroll
            for (int kstep = 0; kstep < 2; kstep++) {
                int idx = (((c * 8 + mt) * 2 + kstep) * 32 + lane) * 4;
                *reinterpret_cast<uint4*>(tile + idx) =
                    make_uint4(regs[c][kstep][0], regs[c][kstep][1],
                               regs[c][kstep][2], regs[c][kstep][3]);
            }
    } else {
        // ---- E path: thread = (yt, kt, nt, lane); 4 fp16 planes, paired ----
        int t = (blockIdx.x - 1024) * 256 + threadIdx.x;   // 131072
        int lane = t & 31;
        int nt   = (t >> 5) & 7;
        int kt   = (t >> 8) & 31;
        int yt   = t >> 13;
        int g = lane >> 2, tg = lane & 3;

        int y = yt * 64 + nt * 8 + g;
        const float4* er = reinterpret_cast<const float4*>(eig) + (size_t)y * GX;

        uint32_t regs[4][2][2];
        #pragma unroll
        for (int kstep = 0; kstep < 2; kstep++) {
            #pragma unroll
            for (int khi = 0; khi < 2; khi++) {
                int xb = kt * 32 + kstep * 16 + khi * 8 + 2 * tg;
                float4 e0 = er[xb];
                float4 e1 = er[xb + 1];
                float pe[4], po[4];
                pe[0] = (e0.x + e0.y + e0.z + e0.w) * 0.25f;
                po[0] = (e1.x + e1.y + e1.z + e1.w) * 0.25f;
                pe[1] = (e0.x - e0.y + e0.z - e0.w) * 0.25f;
                po[1] = (e1.x - e1.y + e1.z - e1.w) * 0.25f;
                pe[2] = (e0.x - e0.z) * 0.5f;   po[2] = (e1.x - e1.z) * 0.5f;   // P1r
                pe[3] = (e0.w - e0.y) * 0.5f;   po[3] = (e1.w - e1.y) * 0.5f;   // P1i
                #pragma unroll
                for (int p = 0; p < 4; p++) regs[p][kstep][khi] = pack_h2(pe[p], po[p]);
            }
        }
        uint32_t* tile = g_E + (size_t)(yt * 32 + kt) * E_TILE_U32;
        #pragma unroll
        for (int p = 0; p < 4; p++)
            #pragma unroll
            for (int kstep = 0; kstep < 2; kstep++) {
                int idx = (((p * 4 + (nt >> 1)) * 2 + kstep) * 32 + lane) * 4 + (nt & 1) * 2;
                *reinterpret_cast<uint2*>(tile + idx) =
                    make_uint2(regs[p][kstep][0], regs[p][kstep][1]);
            }
    }
}

// ---------------------------------------------------------------------------
// GEMM: CTA owns 2 bmt x 2 yt sub-tiles. Per sub-tile 128b x 64 gy-blocks;
// 8 warps (4m x 2n), warp 32b x 32gy. 4-stage bulk+mbarrier ring consumed
// in PAIRS: one wait pair + one unbroken 2-kt MMA run per iteration.
// ---------------------------------------------------------------------------
#define STAGE_U32 (A_TILE_U32 + E_TILE_U32)       // 12288 (49152 B)
#define STAGES 4
#define HDR_U32 256                               // 1024 B header
#define SMEM_BYTES ((HDR_U32 + STAGES * STAGE_U32) * 4)   // 197632

__global__ void __launch_bounds__(256, 1) gemm_freq_kernel(float* __restrict__ out) {
    extern __shared__ uint32_t smem[];
    const uint32_t sbase  = smem_u32(smem);
    const uint32_t full0  = sbase;            // full[s]  at +8s
    const uint32_t empty0 = sbase + 32;       // empty[s] at +8s
    const uint32_t stage0 = sbase + HDR_U32 * 4;

    const int tid  = threadIdx.x;
    const int ytp  = blockIdx.x;   // 0..7
    const int bmtp = blockIdx.y;   // 0..15

    const int warp  = tid >> 5;
    const int lane  = tid & 31;
    const int g     = lane >> 2;
    const int tg    = lane & 3;
    const int warpM = warp & 3;
    const int warpN = warp >> 2;

    if (tid == 0) {
        #pragma unroll
        for (int s = 0; s < STAGES; s++) {
            mbar_init(full0 + 8 * s, 1);
            mbar_init(empty0 + 8 * s, 8);
        }
    }
    __syncthreads();

    auto produce = [&](int gi) {
        int t2 = gi >> 5, kt2 = gi & 31;
        int bsel = t2 >> 1, ysel = bsel ^ (t2 & 1);
        const uint32_t* sA = g_U + (size_t)((bmtp * 2 + bsel) * 32 + kt2) * A_TILE_U32;
        const uint32_t* sE = g_E + (size_t)((ytp * 2 + ysel) * 32 + kt2) * E_TILE_U32;
        int s2 = gi & (STAGES - 1), r2 = gi >> 2;
        if (r2 >= 1) mbar_wait(empty0 + 8 * s2, (uint32_t)(r2 - 1) & 1u);
        uint32_t fb = full0 + 8 * s2;
        mbar_expect_tx(fb, STAGE_U32 * 4);
        uint32_t sa = stage0 + s2 * (STAGE_U32 * 4);
        bulk_g2s(sa, sA, A_TILE_U32 * 4, fb);
        bulk_g2s(sa + A_TILE_U32 * 4, sE, E_TILE_U32 * 4, fb);
    };

    // fill all 4 stages up front (round 0: no empty wait inside produce)
    if (tid == 0) { produce(0); produce(1); produce(2); produce(3); }

    // Non-volatile MMA: ordering via data deps, ptxas may schedule freely.
    #define MMA(ACC, AF, B0, B1)                                                  \
        asm("mma.sync.aligned.m16n8k16.row.col.f32.f16.f16.f32 "                  \
            "{%0,%1,%2,%3}, {%4,%5,%6,%7}, {%8,%9}, {%0,%1,%2,%3};\n"             \
            : "+f"((ACC)[0]), "+f"((ACC)[1]), "+f"((ACC)[2]), "+f"((ACC)[3])      \
            : "r"((AF).x), "r"((AF).y), "r"((AF).z), "r"((AF).w),                 \
              "r"(B0), "r"(B1))

    #define MMA4(ACCSET, AF, EV0, EV1)                                            \
        do {                                                                      \
            MMA(acc[ACCSET][0][0], (AF)[0], (EV0).x, (EV0).y);                    \
            MMA(acc[ACCSET][0][1], (AF)[0], (EV0).z, (EV0).w);                    \
            MMA(acc[ACCSET][0][2], (AF)[0], (EV1).x, (EV1).y);                    \
            MMA(acc[ACCSET][0][3], (AF)[0], (EV1).z, (EV1).w);                    \
            MMA(acc[ACCSET][1][0], (AF)[1], (EV0).x, (EV0).y);                    \
            MMA(acc[ACCSET][1][1], (AF)[1], (EV0).z, (EV0).w);                    \
            MMA(acc[ACCSET][1][2], (AF)[1], (EV1).x, (EV1).y);                    \
            MMA(acc[ACCSET][1][3], (AF)[1], (EV1).z, (EV1).w);                    \
        } while (0)

    for (int t = 0; t < 4; t++) {
        const int bsel = t >> 1, ysel = bsel ^ (t & 1);
        const int bm0  = (bmtp * 2 + bsel) * 128;
        const int bgy0 = (ytp * 2 + ysel) * 64;

        // acc sets: 0=F0, 1=F2, 2=K1, 3=K2, 4=K3
        float acc[5][2][4][4];
        #pragma unroll
        for (int s = 0; s < 5; s++)
            #pragma unroll
            for (int mi = 0; mi < 2; mi++)
                #pragma unroll
                for (int ni = 0; ni < 4; ni++)
                    #pragma unroll
                    for (int q = 0; q < 4; q++) acc[s][mi][ni][q] = 0.0f;

        for (int ktp = 0; ktp < 16; ktp++) {
            const int gi0 = t * 32 + ktp * 2;           // even; pair (gi0, gi0+1)
            const int s0  = gi0 & (STAGES - 1);         // 0 or 2
            const uint32_t par = (uint32_t)(gi0 >> 2) & 1u;  // same for both of pair

            mbar_wait(full0 + 8 * s0, par);
            mbar_wait(full0 + 8 * (s0 + 1), par);

            // unbroken 2-kt MMA run
            #pragma unroll
            for (int half = 0; half < 2; half++) {
                const uint32_t* base = smem + HDR_U32 + (s0 + half) * STAGE_U32;
                const uint4* A4 = reinterpret_cast<const uint4*>(base);
                const uint4* E4 = reinterpret_cast<const uint4*>(base + A_TILE_U32);

                #pragma unroll
                for (int kstep = 0; kstep < 2; kstep++) {
                    // A comps: 0=u0, 1=u2, 2=u1r, 3=u1i
                    uint4 uf[4][2];
                    #pragma unroll
                    for (int c = 0; c < 4; c++)
                        #pragma unroll
                        for (int mi = 0; mi < 2; mi++)
                            uf[c][mi] = A4[((c * 8 + warpM * 2 + mi) * 2 + kstep) * 32 + lane];
                    // derived u1s = u1r + u1i
                    uint4 us[2];
                    us[0] = hadd2u4(uf[2][0], uf[3][0]);
                    us[1] = hadd2u4(uf[2][1], uf[3][1]);

                    #define ELOAD(p, nip) E4[(((p) * 4 + warpN * 2 + (nip)) * 2 + kstep) * 32 + lane]
                    // slot F0: P0 * u0
                    {
                        uint4 e0 = ELOAD(0, 0), e1 = ELOAD(0, 1);
                        MMA4(0, uf[0], e0, e1);
                    }
                    // slot F2: P2 * u2
                    {
                        uint4 e0 = ELOAD(1, 0), e1 = ELOAD(1, 1);
                        MMA4(1, uf[1], e0, e1);
                    }
                    uint4 r0 = ELOAD(2, 0), r1 = ELOAD(2, 1);
                    uint4 i0 = ELOAD(3, 0), i1 = ELOAD(3, 1);
                    #undef ELOAD
                    // slot K1: P1r * u1s
                    MMA4(2, us, r0, r1);
                    // slot K2: Pd * u1r,  Pd = P1i - P1r
                    {
                        uint4 d0 = hsub2u4(i0, r0);
                        uint4 d1 = hsub2u4(i1, r1);
                        MMA4(3, uf[2], d0, d1);
                    }
                    // slot K3: Ps * u1i,  Ps = P1i + P1r
                    {
                        uint4 s0v = hadd2u4(i0, r0);
                        uint4 s1v = hadd2u4(i1, r1);
                        MMA4(4, uf[3], s0v, s1v);
                    }
                }
            }
            if (lane == 0) {
                mbar_arrive(empty0 + 8 * s0);
                mbar_arrive(empty0 + 8 * (s0 + 1));
            }
            // refill the two stages just released (consumed 2 pairs from now)
            if (tid == 0) {
                if (gi0 + 4 < 128) produce(gi0 + 4);
                if (gi0 + 5 < 128) produce(gi0 + 5);
            }
        }

        // Epilogue: Gauss recombine + inverse-DFT butterfly.
        #pragma unroll
        for (int mi = 0; mi < 2; mi++) {
            #pragma unroll
            for (int ni = 0; ni < 4; ni++) {
                #pragma unroll
                for (int h = 0; h < 2; h++) {
                    #pragma unroll
                    for (int q = 0; q < 2; q++) {
                        int row = bm0 + warpM * 32 + mi * 16 + g + h * 8;
                        int gy  = bgy0 + warpN * 32 + ni * 8 + 2 * tg + q;
                        float F0 = acc[0][mi][ni][2 * h + q];
                        float F2 = acc[1][mi][ni][2 * h + q];
                        float K1 = acc[2][mi][ni][2 * h + q];
                        float K2 = acc[3][mi][ni][2 * h + q];
                        float K3 = acc[4][mi][ni][2 * h + q];
                        float F1r = K1 - K3;
                        float F1i = K1 + K2;
                        float4 o;
                        o.x = F0 + F1r + F2;
                        o.y = F0 - F1i - F2;
                        o.z = F0 - F1r + F2;
                        o.w = F0 + F1i - F2;
                        *reinterpret_cast<float4*>(out + (size_t)row * N_DIM + 4 * gy) = o;
                    }
                }
            }
        }
    }
    #undef MMA4
    #undef MMA
}

// ---------------------------------------------------------------------------
extern "C" void kernel_launch(void* const* d_in, const int* in_sizes, int n_in,
                              void* d_out, int out_size) {
    const float* x   = (const float*)d_in[0];   // (4096, 4096) f32
    const float* eig = (const float*)d_in[1];   // (1024, 1024, 4) f32
    float* out       = (float*)d_out;           // (4096, 4096) f32

    cudaFuncSetAttribute(gemm_freq_kernel,
                         cudaFuncAttributeMaxDynamicSharedMemorySize, SMEM_BYTES);

    transform_kernel<<<1536, 256>>>(x, eig);

    dim3 grid(8, 16);   // 128 CTAs, each 2 bmt x 2 yt sub-tiles => single wave
    gemm_freq_kernel<<<grid, 256, SMEM_BYTES>>>(out);
    (void)in_sizes; (void)n_in; (void)out_size;
}